// round 1
// baseline (speedup 1.0000x reference)
#include <cuda_runtime.h>
#include <math.h>

// Problem constants
#define BSZ 2
#define SEQ 2048
#define EMB 2048
#define NH  16
#define NKV 4
#define DH  128
#define GQ  4
#define MTOT (BSZ*SEQ)          // 4096 rows
#define KVDIM (NKV*DH)          // 512
#define ATT_SCALE 0.08838834764831845f  // 1/sqrt(128)

// Scratch (allocation-free rule: __device__ globals)
__device__ __align__(16) float g_Q[MTOT*EMB];    // 32 MB
__device__ __align__(16) float g_K[MTOT*KVDIM];  //  8 MB
__device__ __align__(16) float g_V[MTOT*KVDIM];  //  8 MB
__device__ __align__(16) float g_O[MTOT*EMB];    // 32 MB

// ---------------------------------------------------------------------------
// SGEMM: C[M,N] = A[M,K] @ W[N,K]^T   (both A and W are K-contiguous, fp32)
// 128x128 tile, BK=8, 256 threads, 8x8 per thread (strided 16 mapping).
// Requires M%128==0, N%128==0, K%8==0 (true for all our shapes).
// ---------------------------------------------------------------------------
__global__ void sgemm_nt(const float* __restrict__ A, const float* __restrict__ W,
                         float* __restrict__ C, int M, int N, int K) {
    __shared__ float As[8][128];
    __shared__ float Ws[8][128];

    const int tid = threadIdx.x;
    const int bm = blockIdx.y * 128;
    const int bn = blockIdx.x * 128;
    const int tr = tid >> 4;       // 0..15
    const int tc = tid & 15;       // 0..15

    // Loader mapping: each thread loads one float4 from A and W per k-step
    const int lrow = tid >> 1;          // 0..127
    const int lkb  = (tid & 1) * 4;     // 0 or 4

    float acc[8][8];
#pragma unroll
    for (int i = 0; i < 8; i++)
#pragma unroll
        for (int j = 0; j < 8; j++) acc[i][j] = 0.f;

    const float* aPtr = A + (size_t)(bm + lrow) * K + lkb;
    const float* wPtr = W + (size_t)(bn + lrow) * K + lkb;

    for (int k0 = 0; k0 < K; k0 += 8) {
        float4 av = *(const float4*)(aPtr + k0);
        float4 wv = *(const float4*)(wPtr + k0);
        __syncthreads();   // previous compute done before smem overwrite
        As[lkb + 0][lrow] = av.x; As[lkb + 1][lrow] = av.y;
        As[lkb + 2][lrow] = av.z; As[lkb + 3][lrow] = av.w;
        Ws[lkb + 0][lrow] = wv.x; Ws[lkb + 1][lrow] = wv.y;
        Ws[lkb + 2][lrow] = wv.z; Ws[lkb + 3][lrow] = wv.w;
        __syncthreads();

#pragma unroll
        for (int kk = 0; kk < 8; kk++) {
            float ra[8], rw[8];
#pragma unroll
            for (int i = 0; i < 8; i++) ra[i] = As[kk][tr + 16 * i];
#pragma unroll
            for (int j = 0; j < 8; j++) rw[j] = Ws[kk][tc + 16 * j];
#pragma unroll
            for (int i = 0; i < 8; i++)
#pragma unroll
                for (int j = 0; j < 8; j++) acc[i][j] += ra[i] * rw[j];
        }
    }

#pragma unroll
    for (int i = 0; i < 8; i++) {
        const int r = bm + tr + 16 * i;
#pragma unroll
        for (int j = 0; j < 8; j++) {
            C[(size_t)r * N + bn + tc + 16 * j] = acc[i][j];
        }
    }
}

// ---------------------------------------------------------------------------
// Flash attention (causal, GQA). One block = (q-tile of 64, head, batch).
// fp32 SIMT. Q/K in smem k-major (pad 65), V row-major, S tile 64x65,
// O accumulator in registers (4 rows x 8 cols per thread), online softmax.
// ---------------------------------------------------------------------------
#define AQ 64
#define AK 64
// smem floats: Qs 128*65 + Ks 128*65 + Vs 64*128 + Ss 64*65 + m/l/c 3*64
#define ATTN_SMEM_FLOATS (128*65 + 128*65 + 64*128 + 64*65 + 3*64)
#define ATTN_SMEM_BYTES  (ATTN_SMEM_FLOATS * 4)

__global__ void attn_kernel(const float* __restrict__ Q, const float* __restrict__ K,
                            const float* __restrict__ V, float* __restrict__ O) {
    const int qt = blockIdx.x;      // 0..31
    const int h  = blockIdx.y;      // 0..15
    const int b  = blockIdx.z;      // 0..1
    const int kvh = h / GQ;

    extern __shared__ float sm[];
    float* Qs   = sm;                    // [128][65]  Qs[k*65 + r]
    float* Ks   = Qs + 128 * 65;         // [128][65]  Ks[k*65 + c]
    float* Vs   = Ks + 128 * 65;         // [64][128]  Vs[j*128 + d]
    float* Ss   = Vs + 64 * 128;         // [64][65]
    float* mrow = Ss + 64 * 65;          // [64]
    float* lrow = mrow + 64;             // [64]
    float* crow = lrow + 64;             // [64]

    const int tid = threadIdx.x;
    const int tr = tid >> 4;             // 0..15
    const int tc = tid & 15;             // 0..15

    const int qrow0 = b * SEQ + qt * AQ;

    // Load Q tile (transposed into smem)
    for (int idx = tid; idx < AQ * DH; idx += 256) {
        const int r = idx >> 7;          // /128
        const int k = idx & 127;
        Qs[k * 65 + r] = Q[(size_t)(qrow0 + r) * EMB + h * DH + k];
    }
    if (tid < 64) { mrow[tid] = -INFINITY; lrow[tid] = 0.f; }

    float oacc[4][8];
#pragma unroll
    for (int i = 0; i < 4; i++)
#pragma unroll
        for (int j = 0; j < 8; j++) oacc[i][j] = 0.f;

    for (int kt = 0; kt <= qt; kt++) {
        const int krow0 = b * SEQ + kt * AK;
        // Load K (transposed) and V tiles
        for (int idx = tid; idx < AK * DH; idx += 256) {
            const int c = idx >> 7;
            const int k = idx & 127;
            const float kval = K[(size_t)(krow0 + c) * KVDIM + kvh * DH + k];
            Ks[k * 65 + c] = kval;
            Vs[idx] = V[(size_t)(krow0 + c) * KVDIM + kvh * DH + k];
        }
        __syncthreads();

        // S = Q @ K^T  (4x4 per thread, strided-16)
        float sacc[4][4];
#pragma unroll
        for (int i = 0; i < 4; i++)
#pragma unroll
            for (int j = 0; j < 4; j++) sacc[i][j] = 0.f;

        for (int k = 0; k < DH; k++) {
            float qa[4], kb[4];
#pragma unroll
            for (int i = 0; i < 4; i++) qa[i] = Qs[k * 65 + tr + 16 * i];
#pragma unroll
            for (int j = 0; j < 4; j++) kb[j] = Ks[k * 65 + tc + 16 * j];
#pragma unroll
            for (int i = 0; i < 4; i++)
#pragma unroll
                for (int j = 0; j < 4; j++) sacc[i][j] += qa[i] * kb[j];
        }

        // scale + causal mask + store
#pragma unroll
        for (int i = 0; i < 4; i++) {
            const int ri = tr + 16 * i;
            const int gq = qt * AQ + ri;
#pragma unroll
            for (int j = 0; j < 4; j++) {
                const int cj = tc + 16 * j;
                const int gk = kt * AK + cj;
                float val = sacc[i][j] * ATT_SCALE;
                if (gk > gq) val = -INFINITY;
                Ss[ri * 65 + cj] = val;
            }
        }
        __syncthreads();

        // per-row max + correction
        if (tid < 64) {
            float mold = mrow[tid];
            float rm = -INFINITY;
#pragma unroll 8
            for (int c = 0; c < AK; c++) rm = fmaxf(rm, Ss[tid * 65 + c]);
            const float mnew = fmaxf(mold, rm);
            crow[tid] = expf(mold - mnew);   // 0 on first tile (mold=-inf)
            mrow[tid] = mnew;
        }
        __syncthreads();

        // P = exp(S - m); rescale O accumulators
#pragma unroll
        for (int i = 0; i < 4; i++) {
            const int ri = tr + 16 * i;
            const float corr = crow[ri];
            const float mv = mrow[ri];
#pragma unroll
            for (int j = 0; j < 8; j++) oacc[i][j] *= corr;
#pragma unroll
            for (int j = 0; j < 4; j++) {
                const int cj = tc + 16 * j;
                Ss[ri * 65 + cj] = expf(Ss[ri * 65 + cj] - mv);
            }
        }
        __syncthreads();

        // row sums -> l
        if (tid < 64) {
            float s = 0.f;
#pragma unroll 8
            for (int c = 0; c < AK; c++) s += Ss[tid * 65 + c];
            lrow[tid] = lrow[tid] * crow[tid] + s;
        }

        // O += P @ V  (4 rows x 8 cols per thread, strided-16 cols)
        for (int jj = 0; jj < AK; jj++) {
            float pv[4], vv[8];
#pragma unroll
            for (int i = 0; i < 4; i++) pv[i] = Ss[(tr + 16 * i) * 65 + jj];
#pragma unroll
            for (int j = 0; j < 8; j++) vv[j] = Vs[jj * 128 + tc + 16 * j];
#pragma unroll
            for (int i = 0; i < 4; i++)
#pragma unroll
                for (int j = 0; j < 8; j++) oacc[i][j] += pv[i] * vv[j];
        }
        __syncthreads();
    }

    // epilogue: divide by l, write O as [B,S,H*D]
#pragma unroll
    for (int i = 0; i < 4; i++) {
        const int ri = tr + 16 * i;
        const float inv = 1.f / lrow[ri];
#pragma unroll
        for (int j = 0; j < 8; j++) {
            const int d = tc + 16 * j;
            O[(size_t)(qrow0 + ri) * EMB + h * DH + d] = oacc[i][j] * inv;
        }
    }
}

// ---------------------------------------------------------------------------
extern "C" void kernel_launch(void* const* d_in, const int* in_sizes, int n_in,
                              void* d_out, int out_size) {
    const float* x  = (const float*)d_in[0];
    const float* Wq = (const float*)d_in[1];
    const float* Wk = (const float*)d_in[2];
    const float* Wv = (const float*)d_in[3];
    const float* Wo = (const float*)d_in[4];
    float* out = (float*)d_out;

    void *pQ, *pK, *pV, *pO;
    cudaGetSymbolAddress(&pQ, g_Q);
    cudaGetSymbolAddress(&pK, g_K);
    cudaGetSymbolAddress(&pV, g_V);
    cudaGetSymbolAddress(&pO, g_O);

    cudaFuncSetAttribute(attn_kernel, cudaFuncAttributeMaxDynamicSharedMemorySize,
                         ATTN_SMEM_BYTES);

    dim3 blk(256);

    // Projections
    sgemm_nt<<<dim3(EMB / 128, MTOT / 128), blk>>>(x, Wq, (float*)pQ, MTOT, EMB, EMB);
    sgemm_nt<<<dim3(KVDIM / 128, MTOT / 128), blk>>>(x, Wk, (float*)pK, MTOT, KVDIM, EMB);
    sgemm_nt<<<dim3(KVDIM / 128, MTOT / 128), blk>>>(x, Wv, (float*)pV, MTOT, KVDIM, EMB);

    // Attention
    attn_kernel<<<dim3(SEQ / AQ, NH, BSZ), blk, ATTN_SMEM_BYTES>>>(
        (const float*)pQ, (const float*)pK, (const float*)pV, (float*)pO);

    // Output projection
    sgemm_nt<<<dim3(EMB / 128, MTOT / 128), blk>>>((const float*)pO, Wo, out, MTOT, EMB, EMB);
}

// round 2
// speedup vs baseline: 4.1619x; 4.1619x over previous
#include <cuda_runtime.h>
#include <math.h>
#include <stdint.h>

// Problem constants
#define BSZ 2
#define SEQ 2048
#define EMB 2048
#define NH  16
#define NKV 4
#define DH  128
#define GQ  4
#define MTOT (BSZ*SEQ)          // 4096 rows
#define KVDIM (NKV*DH)          // 512
#define ATT_SCALE 0.08838834764831845f  // 1/sqrt(128)

// Scratch (allocation-free rule: __device__ globals)
__device__ __align__(16) float g_Q[MTOT*EMB];    // 32 MB
__device__ __align__(16) float g_K[MTOT*KVDIM];  //  8 MB
__device__ __align__(16) float g_V[MTOT*KVDIM];  //  8 MB
__device__ __align__(16) float g_O[MTOT*EMB];    // 32 MB

__device__ __forceinline__ uint32_t f2tf32(float x) {
    uint32_t r;
    asm("cvt.rna.tf32.f32 %0, %1;" : "=r"(r) : "f"(x));
    return r;
}

__device__ __forceinline__ void mma_tf32(float c[4],
                                         uint32_t a0, uint32_t a1, uint32_t a2, uint32_t a3,
                                         uint32_t b0, uint32_t b1) {
    asm volatile(
        "mma.sync.aligned.m16n8k8.row.col.f32.tf32.tf32.f32 "
        "{%0,%1,%2,%3}, {%4,%5,%6,%7}, {%8,%9}, {%0,%1,%2,%3};"
        : "+f"(c[0]), "+f"(c[1]), "+f"(c[2]), "+f"(c[3])
        : "r"(a0), "r"(a1), "r"(a2), "r"(a3), "r"(b0), "r"(b1));
}

// ---------------------------------------------------------------------------
// TF32 GEMM: C[M,N] = A[M,K] @ W[N,K]^T
// 128x128 block tile, BK=32, 256 threads (8 warps, 2x4), warp tile 64x32.
// Fragments loaded directly from smem (pad 36 -> conflict-free frag loads).
// ---------------------------------------------------------------------------
#define GPAD 36
__global__ __launch_bounds__(256, 2)
void gemm_tf32(const float* __restrict__ A, const float* __restrict__ W,
               float* __restrict__ C, int M, int N, int K) {
    __shared__ uint32_t As[128 * GPAD];
    __shared__ uint32_t Ws[128 * GPAD];

    const int tid = threadIdx.x;
    const int lane = tid & 31;
    const int wrp = tid >> 5;
    const int g = lane >> 2;   // 0..7
    const int q = lane & 3;    // 0..3
    const int wm = wrp >> 2;   // 0..1
    const int wn = wrp & 3;    // 0..3
    const int bm = blockIdx.y * 128;
    const int bn = blockIdx.x * 128;

    float acc[4][4][4];
#pragma unroll
    for (int mt = 0; mt < 4; mt++)
#pragma unroll
        for (int nt = 0; nt < 4; nt++)
#pragma unroll
            for (int e = 0; e < 4; e++) acc[mt][nt][e] = 0.f;

    // loader: 4 float4 per matrix per k-chunk.  idx = tid + 256*i
    // row = idx>>3 (0..127), kc = (idx&7)*4 (0..28)
    float4 ra[4], rw[4];
    {
#pragma unroll
        for (int i = 0; i < 4; i++) {
            const int idx = tid + 256 * i;
            const int row = idx >> 3;
            const int kc = (idx & 7) * 4;
            ra[i] = *(const float4*)&A[(size_t)(bm + row) * K + kc];
            rw[i] = *(const float4*)&W[(size_t)(bn + row) * K + kc];
        }
    }

    for (int k0 = 0; k0 < K; k0 += 32) {
        __syncthreads();   // previous compute done before smem overwrite
#pragma unroll
        for (int i = 0; i < 4; i++) {
            const int idx = tid + 256 * i;
            const int row = idx >> 3;
            const int kc = (idx & 7) * 4;
            As[row * GPAD + kc + 0] = f2tf32(ra[i].x);
            As[row * GPAD + kc + 1] = f2tf32(ra[i].y);
            As[row * GPAD + kc + 2] = f2tf32(ra[i].z);
            As[row * GPAD + kc + 3] = f2tf32(ra[i].w);
            Ws[row * GPAD + kc + 0] = f2tf32(rw[i].x);
            Ws[row * GPAD + kc + 1] = f2tf32(rw[i].y);
            Ws[row * GPAD + kc + 2] = f2tf32(rw[i].z);
            Ws[row * GPAD + kc + 3] = f2tf32(rw[i].w);
        }
        __syncthreads();

        if (k0 + 32 < K) {
            const int kn = k0 + 32;
#pragma unroll
            for (int i = 0; i < 4; i++) {
                const int idx = tid + 256 * i;
                const int row = idx >> 3;
                const int kc = (idx & 7) * 4;
                ra[i] = *(const float4*)&A[(size_t)(bm + row) * K + kn + kc];
                rw[i] = *(const float4*)&W[(size_t)(bn + row) * K + kn + kc];
            }
        }

#pragma unroll
        for (int ks = 0; ks < 4; ks++) {
            const int kb = ks * 8;
            uint32_t bf[4][2];
#pragma unroll
            for (int nt = 0; nt < 4; nt++) {
                const int n = wn * 32 + nt * 8 + g;
                bf[nt][0] = Ws[n * GPAD + kb + q];
                bf[nt][1] = Ws[n * GPAD + kb + q + 4];
            }
#pragma unroll
            for (int mt = 0; mt < 4; mt++) {
                const int row = wm * 64 + mt * 16 + g;
                uint32_t a0 = As[row * GPAD + kb + q];
                uint32_t a1 = As[(row + 8) * GPAD + kb + q];
                uint32_t a2 = As[row * GPAD + kb + q + 4];
                uint32_t a3 = As[(row + 8) * GPAD + kb + q + 4];
#pragma unroll
                for (int nt = 0; nt < 4; nt++)
                    mma_tf32(acc[mt][nt], a0, a1, a2, a3, bf[nt][0], bf[nt][1]);
            }
        }
    }

    // epilogue
#pragma unroll
    for (int mt = 0; mt < 4; mt++) {
        const int row = bm + wm * 64 + mt * 16 + g;
#pragma unroll
        for (int nt = 0; nt < 4; nt++) {
            const int col = bn + wn * 32 + nt * 8 + 2 * q;
            float2 v0 = make_float2(acc[mt][nt][0], acc[mt][nt][1]);
            float2 v1 = make_float2(acc[mt][nt][2], acc[mt][nt][3]);
            *(float2*)&C[(size_t)row * N + col] = v0;
            *(float2*)&C[(size_t)(row + 8) * N + col] = v1;
        }
    }
}

// ---------------------------------------------------------------------------
// Flash attention (causal, GQA) with tf32 mma.
// Block: 256 threads (8 warps), q-tile 128 (16 rows/warp), k-tile 64.
// Q lives in A-fragments in registers; K/V row-major in smem;
// P staged in per-warp-private smem region (no block sync needed for P).
// ---------------------------------------------------------------------------
#define KVPAD 132
#define PPAD  68
#define SM_KS 0
#define SM_VS (64 * KVPAD)
#define SM_PS (2 * 64 * KVPAD)
#define ATTN_SMEM_U32 (2 * 64 * KVPAD + 128 * PPAD)
#define ATTN_SMEM_BYTES (ATTN_SMEM_U32 * 4)

__global__ __launch_bounds__(256, 1)
void attn_tf32(const float* __restrict__ Q, const float* __restrict__ K,
               const float* __restrict__ V, float* __restrict__ O) {
    const int qt = (gridDim.x - 1) - blockIdx.x;  // reversed: big tiles first
    const int h  = blockIdx.y;
    const int b  = blockIdx.z;
    const int kvh = h / GQ;

    extern __shared__ uint32_t smu[];
    uint32_t* Ks = smu + SM_KS;   // [64][132] (row=kcol, col=d)
    uint32_t* Vs = smu + SM_VS;   // [64][132]
    uint32_t* Ps = smu + SM_PS;   // [128][68] (row=qrow-in-tile, col=kcol)

    const int tid = threadIdx.x;
    const int lane = tid & 31;
    const int w = tid >> 5;       // warp 0..7
    const int g = lane >> 2;
    const int q = lane & 3;

    const int qrow0 = b * SEQ + qt * 128;

    // Q fragments: 16 k-tiles over d=128, held in registers
    uint32_t qa[16][4];
    {
        const float* qb = Q + (size_t)(qrow0 + w * 16) * EMB + h * DH;
#pragma unroll
        for (int kt16 = 0; kt16 < 16; kt16++) {
            const int d0 = kt16 * 8;
            qa[kt16][0] = f2tf32(qb[(size_t)g * EMB + d0 + q]);
            qa[kt16][1] = f2tf32(qb[(size_t)(g + 8) * EMB + d0 + q]);
            qa[kt16][2] = f2tf32(qb[(size_t)g * EMB + d0 + q + 4]);
            qa[kt16][3] = f2tf32(qb[(size_t)(g + 8) * EMB + d0 + q + 4]);
        }
    }

    float o[16][4];
#pragma unroll
    for (int nt = 0; nt < 16; nt++)
#pragma unroll
        for (int e = 0; e < 4; e++) o[nt][e] = 0.f;

    float m0 = -INFINITY, m1 = -INFINITY, l0 = 0.f, l1 = 0.f;

    const int qg0 = qt * 128 + w * 16 + g;   // global q index for rows (c0,c1)
    const int qg1 = qg0 + 8;

    const int nkt = 2 * qt + 2;
    for (int kt = 0; kt < nkt; kt++) {
        // ---- load K/V tile (64 rows x 128 d) ----
        __syncthreads();   // previous PV done reading Vs
        {
            const float* kb = K + (size_t)(b * SEQ + kt * 64) * KVDIM + kvh * DH;
            const float* vb = V + (size_t)(b * SEQ + kt * 64) * KVDIM + kvh * DH;
#pragma unroll
            for (int i = 0; i < 8; i++) {
                const int idx = tid + 256 * i;      // 0..2047
                const int row = idx >> 5;           // 0..63
                const int dc = (idx & 31) * 4;      // 0..124
                float4 kv = *(const float4*)&kb[(size_t)row * KVDIM + dc];
                float4 vv = *(const float4*)&vb[(size_t)row * KVDIM + dc];
                Ks[row * KVPAD + dc + 0] = f2tf32(kv.x);
                Ks[row * KVPAD + dc + 1] = f2tf32(kv.y);
                Ks[row * KVPAD + dc + 2] = f2tf32(kv.z);
                Ks[row * KVPAD + dc + 3] = f2tf32(kv.w);
                Vs[row * KVPAD + dc + 0] = f2tf32(vv.x);
                Vs[row * KVPAD + dc + 1] = f2tf32(vv.y);
                Vs[row * KVPAD + dc + 2] = f2tf32(vv.z);
                Vs[row * KVPAD + dc + 3] = f2tf32(vv.w);
            }
        }
        __syncthreads();

        // ---- S = Q @ K^T (16 rows x 64 cols per warp) ----
        float s[8][4];
#pragma unroll
        for (int nt = 0; nt < 8; nt++)
#pragma unroll
            for (int e = 0; e < 4; e++) s[nt][e] = 0.f;

#pragma unroll
        for (int ks = 0; ks < 16; ks++) {
            const int kd = ks * 8;
#pragma unroll
            for (int nt = 0; nt < 8; nt++) {
                uint32_t b0 = Ks[(nt * 8 + g) * KVPAD + kd + q];
                uint32_t b1 = Ks[(nt * 8 + g) * KVPAD + kd + q + 4];
                mma_tf32(s[nt], qa[ks][0], qa[ks][1], qa[ks][2], qa[ks][3], b0, b1);
            }
        }

        // ---- scale + causal mask ----
#pragma unroll
        for (int nt = 0; nt < 8; nt++) {
            const int kg = kt * 64 + nt * 8 + 2 * q;
            s[nt][0] = (kg     > qg0) ? -INFINITY : s[nt][0] * ATT_SCALE;
            s[nt][1] = (kg + 1 > qg0) ? -INFINITY : s[nt][1] * ATT_SCALE;
            s[nt][2] = (kg     > qg1) ? -INFINITY : s[nt][2] * ATT_SCALE;
            s[nt][3] = (kg + 1 > qg1) ? -INFINITY : s[nt][3] * ATT_SCALE;
        }

        // ---- online softmax ----
        float rm0 = -INFINITY, rm1 = -INFINITY;
#pragma unroll
        for (int nt = 0; nt < 8; nt++) {
            rm0 = fmaxf(rm0, fmaxf(s[nt][0], s[nt][1]));
            rm1 = fmaxf(rm1, fmaxf(s[nt][2], s[nt][3]));
        }
        rm0 = fmaxf(rm0, __shfl_xor_sync(0xffffffffu, rm0, 1));
        rm0 = fmaxf(rm0, __shfl_xor_sync(0xffffffffu, rm0, 2));
        rm1 = fmaxf(rm1, __shfl_xor_sync(0xffffffffu, rm1, 1));
        rm1 = fmaxf(rm1, __shfl_xor_sync(0xffffffffu, rm1, 2));

        const float mn0 = fmaxf(m0, rm0);
        const float mn1 = fmaxf(m1, rm1);
        const float c0 = __expf(m0 - mn0);
        const float c1 = __expf(m1 - mn1);
        m0 = mn0; m1 = mn1;

        float rs0 = 0.f, rs1 = 0.f;
        uint32_t* pw0 = Ps + (size_t)(w * 16 + g) * PPAD;
        uint32_t* pw1 = Ps + (size_t)(w * 16 + g + 8) * PPAD;
#pragma unroll
        for (int nt = 0; nt < 8; nt++) {
            const float p00 = __expf(s[nt][0] - mn0);
            const float p01 = __expf(s[nt][1] - mn0);
            const float p10 = __expf(s[nt][2] - mn1);
            const float p11 = __expf(s[nt][3] - mn1);
            rs0 += p00 + p01;
            rs1 += p10 + p11;
            const int cc = nt * 8 + 2 * q;
            pw0[cc] = f2tf32(p00); pw0[cc + 1] = f2tf32(p01);
            pw1[cc] = f2tf32(p10); pw1[cc + 1] = f2tf32(p11);
        }
        rs0 += __shfl_xor_sync(0xffffffffu, rs0, 1);
        rs0 += __shfl_xor_sync(0xffffffffu, rs0, 2);
        rs1 += __shfl_xor_sync(0xffffffffu, rs1, 1);
        rs1 += __shfl_xor_sync(0xffffffffu, rs1, 2);
        l0 = l0 * c0 + rs0;
        l1 = l1 * c1 + rs1;

#pragma unroll
        for (int nt = 0; nt < 16; nt++) {
            o[nt][0] *= c0; o[nt][1] *= c0;
            o[nt][2] *= c1; o[nt][3] *= c1;
        }

        __syncwarp();   // P visible within warp (P region is warp-private)

        // ---- O += P @ V ----
#pragma unroll
        for (int ks = 0; ks < 8; ks++) {
            const int kc = ks * 8;
            uint32_t a0 = Ps[(w * 16 + g) * PPAD + kc + q];
            uint32_t a1 = Ps[(w * 16 + g + 8) * PPAD + kc + q];
            uint32_t a2 = Ps[(w * 16 + g) * PPAD + kc + q + 4];
            uint32_t a3 = Ps[(w * 16 + g + 8) * PPAD + kc + q + 4];
#pragma unroll
            for (int nt = 0; nt < 16; nt++) {
                uint32_t b0 = Vs[(kc + q) * KVPAD + nt * 8 + g];
                uint32_t b1 = Vs[(kc + q + 4) * KVPAD + nt * 8 + g];
                mma_tf32(o[nt], a0, a1, a2, a3, b0, b1);
            }
        }
    }

    // ---- epilogue ----
    const float inv0 = 1.f / l0;
    const float inv1 = 1.f / l1;
    float* ob = O + (size_t)(qrow0 + w * 16) * EMB + h * DH;
#pragma unroll
    for (int nt = 0; nt < 16; nt++) {
        const int d = nt * 8 + 2 * q;
        float2 v0 = make_float2(o[nt][0] * inv0, o[nt][1] * inv0);
        float2 v1 = make_float2(o[nt][2] * inv1, o[nt][3] * inv1);
        *(float2*)&ob[(size_t)g * EMB + d] = v0;
        *(float2*)&ob[(size_t)(g + 8) * EMB + d] = v1;
    }
}

// ---------------------------------------------------------------------------
extern "C" void kernel_launch(void* const* d_in, const int* in_sizes, int n_in,
                              void* d_out, int out_size) {
    const float* x  = (const float*)d_in[0];
    const float* Wq = (const float*)d_in[1];
    const float* Wk = (const float*)d_in[2];
    const float* Wv = (const float*)d_in[3];
    const float* Wo = (const float*)d_in[4];
    float* out = (float*)d_out;

    void *pQ, *pK, *pV, *pO;
    cudaGetSymbolAddress(&pQ, g_Q);
    cudaGetSymbolAddress(&pK, g_K);
    cudaGetSymbolAddress(&pV, g_V);
    cudaGetSymbolAddress(&pO, g_O);

    cudaFuncSetAttribute(attn_tf32, cudaFuncAttributeMaxDynamicSharedMemorySize,
                         ATTN_SMEM_BYTES);

    dim3 blk(256);

    // Projections
    gemm_tf32<<<dim3(EMB / 128, MTOT / 128), blk>>>(x, Wq, (float*)pQ, MTOT, EMB, EMB);
    gemm_tf32<<<dim3(KVDIM / 128, MTOT / 128), blk>>>(x, Wk, (float*)pK, MTOT, KVDIM, EMB);
    gemm_tf32<<<dim3(KVDIM / 128, MTOT / 128), blk>>>(x, Wv, (float*)pV, MTOT, KVDIM, EMB);

    // Attention
    attn_tf32<<<dim3(SEQ / 128, NH, BSZ), blk, ATTN_SMEM_BYTES>>>(
        (const float*)pQ, (const float*)pK, (const float*)pV, (float*)pO);

    // Output projection
    gemm_tf32<<<dim3(EMB / 128, MTOT / 128), blk>>>((const float*)pO, Wo, out, MTOT, EMB, EMB);
}